// round 1
// baseline (speedup 1.0000x reference)
#include <cuda_runtime.h>

#define C_ 192
#define H_ 256
#define W_ 256
#define NH_ 8
#define HD_ 24
#define S_ 64
#define SCALE_ 0.20412414523193154f

// smem layout (floats)
#define XSH_STRIDE 193
#define QK_STRIDE 385
#define OFF_XSH 0
#define OFF_QK (64 * XSH_STRIDE)                 // 12352
#define OFF_WSH (OFF_QK + 64 * QK_STRIDE)        // +24640
#define OFF_WV (OFF_WSH + 2 * 16 * 384)          // +12288
#define OFF_VW (OFF_WV + C_ * NH_)               // +1536
#define OFF_G (OFF_VW + NH_ * S_)                // +512
#define OFF_B (OFF_G + C_)
#define SMEM_FLOATS (OFF_B + C_)
#define SMEM_BYTES (SMEM_FLOATS * 4)

__device__ float g_wveff[C_ * NH_];
__device__ float g_bveff[NH_];
__device__ float g_bpmean;

__global__ void precompute_kernel(const float* __restrict__ w_qkv,
                                  const float* __restrict__ b_qkv,
                                  const float* __restrict__ w_proj,
                                  const float* __restrict__ b_proj) {
  __shared__ float wps[C_];
  int k = threadIdx.x;  // 0..191
  float s = 0.f;
  for (int c = 0; c < C_; ++c) s += w_proj[k * C_ + c];
  wps[k] = s * (1.f / C_);
  __syncthreads();
  for (int h = 0; h < NH_; ++h) {
    float acc = 0.f;
    for (int d = 0; d < HD_; ++d)
      acc += w_qkv[k * (3 * C_) + 2 * C_ + h * HD_ + d] * wps[h * HD_ + d];
    g_wveff[k * NH_ + h] = acc;
  }
  if (k < NH_) {
    float acc = 0.f;
    for (int d = 0; d < HD_; ++d)
      acc += b_qkv[2 * C_ + k * HD_ + d] * wps[k * HD_ + d];
    g_bveff[k] = acc;
  }
  if (k == 0) {
    float acc = 0.f;
    for (int c = 0; c < C_; ++c) acc += b_proj[c];
    g_bpmean = acc * (1.f / C_);
  }
}

__global__ __launch_bounds__(256, 1) void swin_fused_kernel(
    const float* __restrict__ x, const float* __restrict__ gamma,
    const float* __restrict__ beta, const float* __restrict__ w_qkv,
    const float* __restrict__ b_qkv, float* __restrict__ out) {
  extern __shared__ float sm[];
  float* xsh = sm + OFF_XSH;    // [64][193] window tokens / xn
  float* qksh = sm + OFF_QK;    // [64][385] q (0..191) and k (192..383)
  float* wsh = sm + OFF_WSH;    // [2][16][384] weight tiles
  float* wvsh = sm + OFF_WV;    // [192][8] w_veff
  float* vwsh = sm + OFF_VW;    // [8][64] vw
  float* gsh = sm + OFF_G;      // gamma
  float* bsh = sm + OFF_B;      // beta

  const int tid = threadIdx.x;
  const int win = blockIdx.x;
  const int bN = win >> 10;
  const int wy = (win >> 5) & 31;
  const int wx = win & 31;
  const float* xbase =
      x + (size_t)bN * C_ * H_ * W_ + (size_t)(wy * 8) * W_ + wx * 8;

  for (int i = tid; i < C_; i += 256) {
    gsh[i] = gamma[i];
    bsh[i] = beta[i];
  }
  for (int i = tid; i < C_ * NH_; i += 256) wvsh[i] = g_wveff[i];

  // ---- load window: [B,C,H,W] -> xsh[s][c]
  #pragma unroll
  for (int u = 0; u < 48; ++u) {
    int idx = tid + u * 256;  // 0..12287
    int c = idx >> 6, s = idx & 63;
    xsh[s * XSH_STRIDE + c] =
        xbase[(size_t)c * (H_ * W_) + (s >> 3) * W_ + (s & 7)];
  }
  __syncthreads();

  // ---- LayerNorm over channel dim (warp: 8 tokens, 4 lanes/token)
  {
    int lane = tid & 31;
    int s = (tid >> 5) * 8 + (lane >> 2);
    int cl = lane & 3;
    float sum = 0.f, sq = 0.f;
    for (int c = cl; c < C_; c += 4) {
      float v = xsh[s * XSH_STRIDE + c];
      sum += v;
      sq += v * v;
    }
    sum += __shfl_xor_sync(0xffffffffu, sum, 1);
    sq += __shfl_xor_sync(0xffffffffu, sq, 1);
    sum += __shfl_xor_sync(0xffffffffu, sum, 2);
    sq += __shfl_xor_sync(0xffffffffu, sq, 2);
    float mu = sum * (1.f / C_);
    float rstd = rsqrtf(sq * (1.f / C_) - mu * mu + 1e-5f);
    for (int c = cl; c < C_; c += 4) {
      float v = xsh[s * XSH_STRIDE + c];
      xsh[s * XSH_STRIDE + c] = (v - mu) * rstd * gsh[c] + bsh[c];
    }
  }
  __syncthreads();

  // ---- Q/K GEMM: qksh[s][j] = xn[s][:] . w_qkv[:, j] + b_qkv[j], j in [0,384)
  {
    const int st = tid >> 5;  // token group 0..7 (tokens st*8..st*8+7)
    const int jt = tid & 31;  // column lane; cols jt + 32*jj
    float acc[8][12];
    #pragma unroll
    for (int i = 0; i < 8; ++i)
      #pragma unroll
      for (int j = 0; j < 12; ++j) acc[i][j] = 0.f;

    float4 pre[6];
    #pragma unroll
    for (int u = 0; u < 6; ++u) {
      int i4 = tid + u * 256;
      int r = i4 / 96, c4 = i4 % 96;
      pre[u] = *reinterpret_cast<const float4*>(w_qkv + (size_t)r * 576 + c4 * 4);
    }
    #pragma unroll
    for (int u = 0; u < 6; ++u) {
      int i4 = tid + u * 256;
      int r = i4 / 96, c4 = i4 % 96;
      *reinterpret_cast<float4*>(wsh + r * 384 + c4 * 4) = pre[u];
    }
    __syncthreads();

    for (int kt = 0; kt < 12; ++kt) {
      const int cur = kt & 1;
      if (kt < 11) {
        #pragma unroll
        for (int u = 0; u < 6; ++u) {
          int i4 = tid + u * 256;
          int r = i4 / 96, c4 = i4 % 96;
          pre[u] = *reinterpret_cast<const float4*>(
              w_qkv + (size_t)((kt + 1) * 16 + r) * 576 + c4 * 4);
        }
      }
      const float* wb = wsh + cur * 6144;
      const float* xb = xsh + st * 8 * XSH_STRIDE + kt * 16;
      #pragma unroll
      for (int kk = 0; kk < 16; ++kk) {
        float xv[8];
        #pragma unroll
        for (int i = 0; i < 8; ++i) xv[i] = xb[i * XSH_STRIDE + kk];
        float wv[12];
        #pragma unroll
        for (int j = 0; j < 12; ++j) wv[j] = wb[kk * 384 + jt + 32 * j];
        #pragma unroll
        for (int i = 0; i < 8; ++i)
          #pragma unroll
          for (int j = 0; j < 12; ++j) acc[i][j] = fmaf(xv[i], wv[j], acc[i][j]);
      }
      if (kt < 11) {
        #pragma unroll
        for (int u = 0; u < 6; ++u) {
          int i4 = tid + u * 256;
          int r = i4 / 96, c4 = i4 % 96;
          *reinterpret_cast<float4*>(wsh + (cur ^ 1) * 6144 + r * 384 + c4 * 4) =
              pre[u];
        }
        __syncthreads();
      }
    }

    #pragma unroll
    for (int j = 0; j < 12; ++j) {
      float bq = b_qkv[jt + 32 * j];
      #pragma unroll
      for (int i = 0; i < 8; ++i)
        qksh[(st * 8 + i) * QK_STRIDE + jt + 32 * j] = acc[i][j] + bq;
    }
  }
  __syncthreads();

  // ---- vw[h][t] = xn[t][:] . w_veff[:,h] + b_veff[h]
  {
    #pragma unroll
    for (int r = 0; r < 2; ++r) {
      int o = tid + r * 256;  // 0..511
      int s = o >> 3, h = o & 7;
      float acc = g_bveff[h];
      for (int c = 0; c < C_; ++c)
        acc = fmaf(xsh[s * XSH_STRIDE + c], wvsh[c * NH_ + h], acc);
      vwsh[h * S_ + s] = acc;
    }
  }
  __syncthreads();

  // ---- attention: logits + softmax + weighted vw sum, all in registers
  {
    const int tt = tid & 15;  // t lane; t = tt + 16*j
    const int ts = tid >> 4;  // s group; s = ts + 16*i
    float outAcc[4] = {0.f, 0.f, 0.f, 0.f};
    for (int h = 0; h < NH_; ++h) {
      float lacc[4][4];
      #pragma unroll
      for (int i = 0; i < 4; ++i)
        #pragma unroll
        for (int j = 0; j < 4; ++j) lacc[i][j] = 0.f;
      const float* qb = qksh + h * HD_;
      const float* kb = qksh + C_ + h * HD_;
      #pragma unroll
      for (int d = 0; d < HD_; ++d) {
        float qv[4], kv[4];
        #pragma unroll
        for (int i = 0; i < 4; ++i) qv[i] = qb[(ts + 16 * i) * QK_STRIDE + d];
        #pragma unroll
        for (int j = 0; j < 4; ++j) kv[j] = kb[(tt + 16 * j) * QK_STRIDE + d];
        #pragma unroll
        for (int i = 0; i < 4; ++i)
          #pragma unroll
          for (int j = 0; j < 4; ++j)
            lacc[i][j] = fmaf(qv[i], kv[j], lacc[i][j]);
      }
      #pragma unroll
      for (int i = 0; i < 4; ++i) {
        float m = fmaxf(fmaxf(lacc[i][0], lacc[i][1]),
                        fmaxf(lacc[i][2], lacc[i][3]));
        m = fmaxf(m, __shfl_xor_sync(0xffffffffu, m, 1, 16));
        m = fmaxf(m, __shfl_xor_sync(0xffffffffu, m, 2, 16));
        m = fmaxf(m, __shfl_xor_sync(0xffffffffu, m, 4, 16));
        m = fmaxf(m, __shfl_xor_sync(0xffffffffu, m, 8, 16));
        float sp = 0.f, spv = 0.f;
        #pragma unroll
        for (int j = 0; j < 4; ++j) {
          float p = __expf((lacc[i][j] - m) * SCALE_);
          sp += p;
          spv = fmaf(p, vwsh[h * S_ + tt + 16 * j], spv);
        }
        #pragma unroll
        for (int o = 1; o < 16; o <<= 1) {
          sp += __shfl_xor_sync(0xffffffffu, sp, o, 16);
          spv += __shfl_xor_sync(0xffffffffu, spv, o, 16);
        }
        outAcc[i] += spv / sp;
      }
    }
    if (tt == 0) {
      float bp = g_bpmean;
      #pragma unroll
      for (int i = 0; i < 4; ++i) {
        int s = ts + 16 * i;
        float v = outAcc[i] + bp;
        float sig = 1.f / (1.f + __expf(-v));
        out[(size_t)bN * (H_ * W_) + (size_t)(wy * 8 + (s >> 3)) * W_ + wx * 8 +
            (s & 7)] = sig;
      }
    }
  }
}

extern "C" void kernel_launch(void* const* d_in, const int* in_sizes, int n_in,
                              void* d_out, int out_size) {
  const float* x = (const float*)d_in[0];
  const float* gamma = (const float*)d_in[1];
  const float* beta = (const float*)d_in[2];
  const float* w_qkv = (const float*)d_in[3];
  const float* b_qkv = (const float*)d_in[4];
  const float* w_proj = (const float*)d_in[5];
  const float* b_proj = (const float*)d_in[6];
  float* out = (float*)d_out;

  cudaFuncSetAttribute(swin_fused_kernel,
                       cudaFuncAttributeMaxDynamicSharedMemorySize, SMEM_BYTES);

  precompute_kernel<<<1, C_>>>(w_qkv, b_qkv, w_proj, b_proj);
  swin_fused_kernel<<<8192, 256, SMEM_BYTES>>>(x, gamma, beta, w_qkv, b_qkv,
                                               out);
}